// round 14
// baseline (speedup 1.0000x reference)
#include <cuda_runtime.h>
#include <cuda_fp16.h>
#include <cstdint>

// ---------------- problem constants ----------------
#define IN_F   4096
#define OUT_F  16384
#define NTOK   64
#define RANK   64

#define BLOCK_M 128          // out-features per CTA
#define KBLK    64           // K elems per pipeline stage
#define STAGES  4
#define THREADS 256
#define NCHUNK_MAIN (IN_F / KBLK)             // 64
#define NCHUNK_TOT  (NCHUNK_MAIN + 1)         // 65 (lora tail chunk)

// ---------------- main-kernel SMEM layout (213 KB, needs opt-in) ----------------
#define P32        68                          // fp32 row pitch (floats)
#define W32_STAGE_F (BLOCK_M * P32)            // 8704 floats
#define W32_STAGE_B (W32_STAGE_F * 4)          // 34816 B
#define OFF_W32    0
#define PH         72                          // fp16 row pitch (halfs)
#define OFF_WH     (STAGES * W32_STAGE_B)      // 139264  (x2 buffers)
#define WH_BYTES   (BLOCK_M * PH * 2)          // 18432
#define OFF_XH     (OFF_WH + 2 * WH_BYTES)     // 176128
#define XH_STAGE_B (NTOK * PH * 2)             // 9216
#define SMEM_BYTES (OFF_XH + STAGES * XH_STAGE_B)  // 212992

// device scratch
__device__ __align__(256) __half g_xh[NTOK * IN_F];    // x in fp16
__device__ __align__(256) __half g_t2h[NTOK * RANK];   // 2*(x@A^T) in fp16
__device__ __align__(256) float  g_part[64 * NTOK * RANK];  // K-slice partials

// ---------------- PTX helpers ----------------
__device__ __forceinline__ uint32_t smem_u32(const void* p) {
    uint32_t a;
    asm("{ .reg .u64 t; cvta.to.shared.u64 t, %1; cvt.u32.u64 %0, t; }" : "=r"(a) : "l"(p));
    return a;
}
__device__ __forceinline__ void cp16(uint32_t dst, const void* src) {
    asm volatile("cp.async.cg.shared.global [%0], [%1], 16;" :: "r"(dst), "l"(src));
}
#define CP_COMMIT() asm volatile("cp.async.commit_group;" ::: "memory")
#define CP_WAIT1()  asm volatile("cp.async.wait_group 1;" ::: "memory")

__device__ __forceinline__ void ldsm4(uint32_t* r, uint32_t addr) {
    asm volatile("ldmatrix.sync.aligned.m8n8.x4.shared.b16 {%0,%1,%2,%3}, [%4];"
                 : "=r"(r[0]), "=r"(r[1]), "=r"(r[2]), "=r"(r[3]) : "r"(addr));
}
__device__ __forceinline__ void mma_f16(float* d, const uint32_t* a,
                                        uint32_t b0, uint32_t b1) {
    asm volatile(
        "mma.sync.aligned.m16n8k16.row.col.f32.f16.f16.f32 "
        "{%0,%1,%2,%3}, {%4,%5,%6,%7}, {%8,%9}, {%0,%1,%2,%3};"
        : "+f"(d[0]), "+f"(d[1]), "+f"(d[2]), "+f"(d[3])
        : "r"(a[0]), "r"(a[1]), "r"(a[2]), "r"(a[3]), "r"(b0), "r"(b1));
}
__device__ __forceinline__ uint32_t h2u(__half2 h) {
    return *reinterpret_cast<uint32_t*>(&h);
}
__device__ __forceinline__ float dot4(float4 a, float4 b) {
    return a.x * b.x + a.y * b.y + a.z * b.z + a.w * b.w;
}

// ---------------- prep: grid 64 (one wave). x2h slice + t2 K-slice partial ----------
// (benched 9.8us — unchanged from R13)
__global__ void __launch_bounds__(256) prep_kernel(const float* __restrict__ x,
                                                   const float* __restrict__ A,
                                                   uint2* __restrict__ xh2,
                                                   float* __restrict__ part) {
    int tid = threadIdx.x;
    int s = blockIdx.x;                       // 0..63
    {
        const float4* x4 = (const float4*)x;
        int base = s * 1024;
#pragma unroll
        for (int i = 0; i < 4; ++i) {
            int idx = base + tid + i * 256;
            float4 v = x4[idx];
            uint2 o;
            o.x = h2u(__floats2half2_rn(v.x, v.y));
            o.y = h2u(__floats2half2_rn(v.z, v.w));
            xh2[idx] = o;
        }
    }
    __shared__ float4 xs[64][17];
    __shared__ float4 as[64][17];
#pragma unroll
    for (int i = 0; i < 4; ++i) {
        int idx = tid + i * 256;
        int row = idx >> 4, c = idx & 15;
        xs[row][c] = ((const float4*)x)[(size_t)row * (IN_F / 4) + s * 16 + c];
        as[row][c] = ((const float4*)A)[(size_t)row * (IN_F / 4) + s * 16 + c];
    }
    __syncthreads();
    int ti = tid >> 4, tj = tid & 15;
    float acc[4][4];
#pragma unroll
    for (int r = 0; r < 4; ++r)
#pragma unroll
        for (int c = 0; c < 4; ++c) acc[r][c] = 0.f;
#pragma unroll
    for (int kc = 0; kc < 16; ++kc) {
        float4 xv[4], av[4];
#pragma unroll
        for (int r = 0; r < 4; ++r) xv[r] = xs[ti * 4 + r][kc];
#pragma unroll
        for (int c = 0; c < 4; ++c) av[c] = as[tj * 4 + c][kc];
#pragma unroll
        for (int r = 0; r < 4; ++r)
#pragma unroll
            for (int c = 0; c < 4; ++c) acc[r][c] += dot4(xv[r], av[c]);
    }
    float* dst = part + (size_t)s * (NTOK * RANK);
#pragma unroll
    for (int r = 0; r < 4; ++r)
#pragma unroll
        for (int c = 0; c < 4; ++c)
            dst[(ti * 4 + r) * RANK + tj * 4 + c] = acc[r][c];
}

// ---------------- reduce: 64 partials -> t2h = fp16(2*sum); 8-way MLP ------------
__global__ void __launch_bounds__(256) reduce_kernel(const float* __restrict__ part,
                                                     __half* __restrict__ t2) {
    int idx = blockIdx.x * 256 + threadIdx.x;     // 0..4095
    float s[8];
#pragma unroll
    for (int j = 0; j < 8; ++j) s[j] = 0.f;
#pragma unroll
    for (int b = 0; b < 64; b += 8)
#pragma unroll
        for (int j = 0; j < 8; ++j)
            s[j] += part[(size_t)(b + j) * 4096 + idx];
    float r = ((s[0] + s[1]) + (s[2] + s[3])) + ((s[4] + s[5]) + (s[6] + s[7]));
    t2[idx] = __float2half_rn(2.0f * r);
}

// ---------------- main fused GEMM ----------------
// 128 CTAs, 256 threads (8 warps: 4M x 2N), KBLK=64, 4-stage cp.async.
// NEW: double-buffered Wh; convert(it+1) overlaps MMA(it); ONE barrier pair per iter.
// Every consume is behind a wait_group(1)+barrier covering that chunk (R5 lesson).
__global__ void __launch_bounds__(THREADS, 1) lora_main_kernel(
    const __half* __restrict__ xh,     // [64,4096] fp16
    const float*  __restrict__ w,      // [16384,4096] fp32
    const float*  __restrict__ lB,     // [16384,64] fp32
    const __half* __restrict__ t2h,    // [64,64] fp16 (incl. 2x scale)
    float* __restrict__ out)           // [64,16384]
{
    extern __shared__ __align__(16) char smem_c[];
    float* smem_f = (float*)smem_c;
    const uint32_t sb = smem_u32(smem_c);
    const int tid  = threadIdx.x;
    const int wid  = tid >> 5;
    const int lane = tid & 31;
    const int g = lane >> 2;
    const int t = lane & 3;
    const int wm = (wid & 3) * 32;    // warp M offset
    const int wn = (wid >> 2) * 32;   // warp N offset (tokens)
    const int m_base = blockIdx.x * BLOCK_M;

    // ---- per-lane ldmatrix offsets ----
    const int a_row  = (lane & 7) + ((lane >> 3) & 1) * 8;
    const uint32_t a_byte = ((lane >> 4) & 1) * 16;
    const uint32_t a_rel0 = (uint32_t)(wm + a_row) * (PH * 2) + a_byte;
    const uint32_t a_rel1 = a_rel0 + 16 * (PH * 2);
    const int b_row  = (lane & 7) + ((lane >> 4) & 1) * 8;
    const uint32_t b_byte = ((lane >> 3) & 1) * 16;
    const uint32_t b_rel0 = (uint32_t)(wn + b_row) * (PH * 2) + b_byte;
    const uint32_t b_rel1 = b_rel0 + 16 * (PH * 2);

    // ---- stage loader: W 128x64 fp32 (8 cp/thread) + X 64x64 fp16 (2 cp/thread) ----
    auto load_stage = [&](int chunk, int stage) {
        const float* a_base; int a_stride;
        const __half* b_base; int b_stride;
        int k0;
        if (chunk < NCHUNK_MAIN) {
            a_base = w + (size_t)m_base * IN_F;  a_stride = IN_F;
            b_base = xh;                         b_stride = IN_F;
            k0 = chunk * KBLK;
        } else {
            a_base = lB + (size_t)m_base * RANK; a_stride = RANK;
            b_base = t2h;                        b_stride = RANK;
            k0 = 0;
        }
        uint32_t s_w = sb + OFF_W32 + (uint32_t)stage * W32_STAGE_B;
#pragma unroll
        for (int i = 0; i < 8; ++i) {
            int idx = tid + i * THREADS;
            int row = idx >> 4, c = idx & 15;
            cp16(s_w + (uint32_t)(row * P32 + c * 4) * 4,
                 a_base + (size_t)row * a_stride + k0 + c * 4);
        }
        uint32_t s_x = sb + OFF_XH + (uint32_t)stage * XH_STAGE_B;
#pragma unroll
        for (int i = 0; i < 2; ++i) {
            int idx = tid + i * THREADS;
            int row = idx >> 3, seg = idx & 7;
            cp16(s_x + (uint32_t)(row * PH + seg * 8) * 2,
                 b_base + (size_t)row * b_stride + k0 + seg * 8);
        }
    };

    // ---- convert: W32[slot] -> Wh[buf]; thread = (row = tid&127, half = tid>>7) ----
    const int cvt_row  = tid & 127;
    const int cvt_half = tid >> 7;
    auto convert = [&](int slot, int buf) {
        const float* srcp = smem_f + slot * W32_STAGE_F + cvt_row * P32 + cvt_half * 32;
        __half* whp = (__half*)(smem_c + OFF_WH + buf * WH_BYTES)
                      + cvt_row * PH + cvt_half * 32;
#pragma unroll
        for (int q = 0; q < 2; ++q) {
            float4 v0 = ((const float4*)(srcp + q * 16))[0];
            float4 v1 = ((const float4*)(srcp + q * 16))[1];
            float4 v2 = ((const float4*)(srcp + q * 16))[2];
            float4 v3 = ((const float4*)(srcp + q * 16))[3];
            uint4 p0, p1;
            p0.x = h2u(__floats2half2_rn(v0.x, v0.y));
            p0.y = h2u(__floats2half2_rn(v0.z, v0.w));
            p0.z = h2u(__floats2half2_rn(v1.x, v1.y));
            p0.w = h2u(__floats2half2_rn(v1.z, v1.w));
            p1.x = h2u(__floats2half2_rn(v2.x, v2.y));
            p1.y = h2u(__floats2half2_rn(v2.z, v2.w));
            p1.z = h2u(__floats2half2_rn(v3.x, v3.y));
            p1.w = h2u(__floats2half2_rn(v3.z, v3.w));
            ((uint4*)(whp + q * 16))[0] = p0;
            ((uint4*)(whp + q * 16 + 8))[0] = p1;
        }
    };

    // ---- prologue: chunks 0,1,2 in flight; chunks 0,1 landed; Wh0 <- chunk 0 ----
    load_stage(0, 0); CP_COMMIT();
    load_stage(1, 1); CP_COMMIT();
    load_stage(2, 2); CP_COMMIT();
    CP_WAIT1();            // own chunks 0,1 complete
    __syncthreads();       // everyone's chunks 0,1 visible
    convert(0, 0);
    __syncthreads();       // Wh0 published

    float d[2][4][4];
#pragma unroll
    for (int mi = 0; mi < 2; ++mi)
#pragma unroll
        for (int ni = 0; ni < 4; ++ni)
#pragma unroll
            for (int r = 0; r < 4; ++r) d[mi][ni][r] = 0.f;

    // ---- mainloop: 65 iterations, ONE wait+barrier per iteration ----
    // entry invariants @ iter it: chunks <= it+1 visible to all; Wh[it&1] = chunk it.
    for (int it = 0; it < NCHUNK_TOT; ++it) {
        // refill chunk it+3 into slot (it+3)&3 (slot of it-1; last read iter it-1)
        {
            int nc = it + 3;
            if (nc < NCHUNK_TOT) load_stage(nc, nc & 3);
            CP_COMMIT();
        }

        // convert chunk it+1 -> Wh[(it+1)&1] (chunk it+1 visible per invariant;
        // Wh[(it+1)&1] last read by MMA at iter it-1, one barrier ago)
        if (it + 1 < NCHUNK_TOT) convert((it + 1) & 3, (it + 1) & 1);

        // MMA chunk it from Wh[it&1], Xh[it&3] — overlaps convert (no barrier between)
        const uint32_t wh_b = sb + OFF_WH + (uint32_t)(it & 1) * WH_BYTES;
        const uint32_t xb   = sb + OFF_XH + (uint32_t)(it & 3) * XH_STAGE_B;
#pragma unroll
        for (int kk = 0; kk < 4; ++kk) {
            const uint32_t k2 = kk * 32;   // 16 halfs = 32B
            uint32_t a0[4], a1[4], bq0[4], bq1[4];
            ldsm4(a0,  wh_b + a_rel0 + k2);
            ldsm4(a1,  wh_b + a_rel1 + k2);
            ldsm4(bq0, xb + b_rel0 + k2);
            ldsm4(bq1, xb + b_rel1 + k2);
            mma_f16(d[0][0], a0, bq0[0], bq0[1]);
            mma_f16(d[0][1], a0, bq0[2], bq0[3]);
            mma_f16(d[0][2], a0, bq1[0], bq1[1]);
            mma_f16(d[0][3], a0, bq1[2], bq1[3]);
            mma_f16(d[1][0], a1, bq0[0], bq0[1]);
            mma_f16(d[1][1], a1, bq0[2], bq0[3]);
            mma_f16(d[1][2], a1, bq1[0], bq1[1]);
            mma_f16(d[1][3], a1, bq1[2], bq1[3]);
        }

        CP_WAIT1();        // own chunk it+2 complete (it+3 may pend)
        __syncthreads();   // publish Wh[(it+1)&1]; everyone's chunk it+2 visible
    }

    // ---- epilogue: D[m][n] -> out[n][m] ----
#pragma unroll
    for (int mi = 0; mi < 2; ++mi) {
#pragma unroll
        for (int ni = 0; ni < 4; ++ni) {
            int m = m_base + wm + mi * 16 + g;
            int n = wn + ni * 8 + 2 * t;
            out[(size_t)n * OUT_F + m]           = d[mi][ni][0];
            out[(size_t)(n + 1) * OUT_F + m]     = d[mi][ni][1];
            out[(size_t)n * OUT_F + m + 8]       = d[mi][ni][2];
            out[(size_t)(n + 1) * OUT_F + m + 8] = d[mi][ni][3];
        }
    }
}

// ---------------- host launch ----------------
extern "C" void kernel_launch(void* const* d_in, const int* in_sizes, int n_in,
                              void* d_out, int out_size) {
    const float* x  = (const float*)d_in[0];   // [64, 4096]
    const float* w  = (const float*)d_in[1];   // [16384, 4096]
    const float* lA = (const float*)d_in[2];   // [64, 4096]
    const float* lB = (const float*)d_in[3];   // [16384, 64]
    float* out = (float*)d_out;                // [64, 16384]

    void* xh_ptr = nullptr;
    void* t2_ptr = nullptr;
    void* part_ptr = nullptr;
    cudaGetSymbolAddress(&xh_ptr, g_xh);
    cudaGetSymbolAddress(&t2_ptr, g_t2h);
    cudaGetSymbolAddress(&part_ptr, g_part);

    prep_kernel<<<64, 256>>>(x, lA, (uint2*)xh_ptr, (float*)part_ptr);
    reduce_kernel<<<16, 256>>>((const float*)part_ptr, (__half*)t2_ptr);

    static int smem_set = 0;
    if (!smem_set) {
        cudaFuncSetAttribute(lora_main_kernel,
                             cudaFuncAttributeMaxDynamicSharedMemorySize, SMEM_BYTES);
        smem_set = 1;
    }
    lora_main_kernel<<<OUT_F / BLOCK_M, THREADS, SMEM_BYTES>>>(
        (const __half*)xh_ptr, w, lB, (const __half*)t2_ptr, out);
}

// round 16
// speedup vs baseline: 1.0429x; 1.0429x over previous
#include <cuda_runtime.h>
#include <cuda_fp16.h>
#include <cstdint>

// ---------------- problem constants ----------------
#define IN_F   4096
#define OUT_F  16384
#define NTOK   64
#define RANK   64

#define BLOCK_M 64           // out-features per CTA (2 CTAs/SM)
#define KBLK    64           // K elems per pipeline stage
#define STAGES  3
#define THREADS 256
#define NCHUNK_MAIN (IN_F / KBLK)             // 64
#define NCHUNK_TOT  (NCHUNK_MAIN + 1)         // 65 (lora tail chunk)

// ---------------- main-kernel SMEM layout (89 KB -> 2 CTAs/SM) ----------------
#define P32        68                          // fp32 row pitch (floats)
#define W32_STAGE_F (BLOCK_M * P32)            // 4352 floats
#define W32_STAGE_B (W32_STAGE_F * 4)          // 17408 B
#define OFF_W32    0
#define PH         72                          // fp16 row pitch (halfs)
#define OFF_WH     (STAGES * W32_STAGE_B)      // 52224  (single buffer)
#define WH_BYTES   (BLOCK_M * PH * 2)          // 9216
#define OFF_XH     (OFF_WH + WH_BYTES)         // 61440
#define XH_STAGE_B (NTOK * PH * 2)             // 9216
#define SMEM_BYTES (OFF_XH + STAGES * XH_STAGE_B)  // 89088

// device scratch
__device__ __align__(256) __half g_xh[NTOK * IN_F];    // x in fp16
__device__ __align__(256) __half g_t2h[NTOK * RANK];   // 2*(x@A^T) in fp16
__device__ __align__(256) float  g_part[64 * NTOK * RANK];  // K-slice partials

// ---------------- PTX helpers ----------------
__device__ __forceinline__ uint32_t smem_u32(const void* p) {
    uint32_t a;
    asm("{ .reg .u64 t; cvta.to.shared.u64 t, %1; cvt.u32.u64 %0, t; }" : "=r"(a) : "l"(p));
    return a;
}
__device__ __forceinline__ void cp16(uint32_t dst, const void* src) {
    asm volatile("cp.async.cg.shared.global [%0], [%1], 16;" :: "r"(dst), "l"(src));
}
#define CP_COMMIT() asm volatile("cp.async.commit_group;" ::: "memory")
#define CP_WAIT1()  asm volatile("cp.async.wait_group 1;" ::: "memory")

__device__ __forceinline__ void ldsm4(uint32_t* r, uint32_t addr) {
    asm volatile("ldmatrix.sync.aligned.m8n8.x4.shared.b16 {%0,%1,%2,%3}, [%4];"
                 : "=r"(r[0]), "=r"(r[1]), "=r"(r[2]), "=r"(r[3]) : "r"(addr));
}
__device__ __forceinline__ void mma_f16(float* d, const uint32_t* a,
                                        uint32_t b0, uint32_t b1) {
    asm volatile(
        "mma.sync.aligned.m16n8k16.row.col.f32.f16.f16.f32 "
        "{%0,%1,%2,%3}, {%4,%5,%6,%7}, {%8,%9}, {%0,%1,%2,%3};"
        : "+f"(d[0]), "+f"(d[1]), "+f"(d[2]), "+f"(d[3])
        : "r"(a[0]), "r"(a[1]), "r"(a[2]), "r"(a[3]), "r"(b0), "r"(b1));
}
__device__ __forceinline__ uint32_t h2u(__half2 h) {
    return *reinterpret_cast<uint32_t*>(&h);
}
__device__ __forceinline__ float dot4(float4 a, float4 b) {
    return a.x * b.x + a.y * b.y + a.z * b.z + a.w * b.w;
}

// ---------------- prep: grid 64 (one wave). x2h slice + t2 K-slice partial ----------
// (benched 9.8us — unchanged)
__global__ void __launch_bounds__(256) prep_kernel(const float* __restrict__ x,
                                                   const float* __restrict__ A,
                                                   uint2* __restrict__ xh2,
                                                   float* __restrict__ part) {
    int tid = threadIdx.x;
    int s = blockIdx.x;                       // 0..63
    {
        const float4* x4 = (const float4*)x;
        int base = s * 1024;
#pragma unroll
        for (int i = 0; i < 4; ++i) {
            int idx = base + tid + i * 256;
            float4 v = x4[idx];
            uint2 o;
            o.x = h2u(__floats2half2_rn(v.x, v.y));
            o.y = h2u(__floats2half2_rn(v.z, v.w));
            xh2[idx] = o;
        }
    }
    __shared__ float4 xs[64][17];
    __shared__ float4 as[64][17];
#pragma unroll
    for (int i = 0; i < 4; ++i) {
        int idx = tid + i * 256;
        int row = idx >> 4, c = idx & 15;
        xs[row][c] = ((const float4*)x)[(size_t)row * (IN_F / 4) + s * 16 + c];
        as[row][c] = ((const float4*)A)[(size_t)row * (IN_F / 4) + s * 16 + c];
    }
    __syncthreads();
    int ti = tid >> 4, tj = tid & 15;
    float acc[4][4];
#pragma unroll
    for (int r = 0; r < 4; ++r)
#pragma unroll
        for (int c = 0; c < 4; ++c) acc[r][c] = 0.f;
#pragma unroll
    for (int kc = 0; kc < 16; ++kc) {
        float4 xv[4], av[4];
#pragma unroll
        for (int r = 0; r < 4; ++r) xv[r] = xs[ti * 4 + r][kc];
#pragma unroll
        for (int c = 0; c < 4; ++c) av[c] = as[tj * 4 + c][kc];
#pragma unroll
        for (int r = 0; r < 4; ++r)
#pragma unroll
            for (int c = 0; c < 4; ++c) acc[r][c] += dot4(xv[r], av[c]);
    }
    float* dst = part + (size_t)s * (NTOK * RANK);
#pragma unroll
    for (int r = 0; r < 4; ++r)
#pragma unroll
        for (int c = 0; c < 4; ++c)
            dst[(ti * 4 + r) * RANK + tj * 4 + c] = acc[r][c];
}

// ---------------- reduce: 64 partials -> t2h = fp16(2*sum); 8-way MLP ------------
__global__ void __launch_bounds__(256) reduce_kernel(const float* __restrict__ part,
                                                     __half* __restrict__ t2) {
    int idx = blockIdx.x * 256 + threadIdx.x;     // 0..4095
    float s[8];
#pragma unroll
    for (int j = 0; j < 8; ++j) s[j] = 0.f;
#pragma unroll
    for (int b = 0; b < 64; b += 8)
#pragma unroll
        for (int j = 0; j < 8; ++j)
            s[j] += part[(size_t)(b + j) * 4096 + idx];
    float r = ((s[0] + s[1]) + (s[2] + s[3])) + ((s[4] + s[5]) + (s[6] + s[7]));
    t2[idx] = __float2half_rn(2.0f * r);
}

// ---------------- main fused GEMM ----------------
// 256 CTAs (2/SM via 89KB smem), 256 threads (8 warps: 4M x 2N), KBLK=64, 3 stages.
// R10-proven two-barrier schedule: wait(1) covers convert(it) at every iteration.
__global__ void __launch_bounds__(THREADS, 2) lora_main_kernel(
    const __half* __restrict__ xh,     // [64,4096] fp16
    const float*  __restrict__ w,      // [16384,4096] fp32
    const float*  __restrict__ lB,     // [16384,64] fp32
    const __half* __restrict__ t2h,    // [64,64] fp16 (incl. 2x scale)
    float* __restrict__ out)           // [64,16384]
{
    extern __shared__ __align__(16) char smem_c[];
    float* smem_f = (float*)smem_c;
    const uint32_t sb = smem_u32(smem_c);
    const int tid  = threadIdx.x;
    const int wid  = tid >> 5;
    const int lane = tid & 31;
    const int g = lane >> 2;
    const int t = lane & 3;
    const int wm = (wid & 3) * 16;    // warp M offset (4 warps x 16 rows)
    const int wn = (wid >> 2) * 32;   // warp N offset (tokens)
    const int m_base = blockIdx.x * BLOCK_M;

    // ---- per-lane ldmatrix offsets ----
    const int a_row  = (lane & 7) + ((lane >> 3) & 1) * 8;
    const uint32_t a_byte = ((lane >> 4) & 1) * 16;
    const uint32_t a_rel = (uint32_t)(wm + a_row) * (PH * 2) + a_byte;
    const int b_row  = (lane & 7) + ((lane >> 4) & 1) * 8;
    const uint32_t b_byte = ((lane >> 3) & 1) * 16;
    const uint32_t b_rel0 = (uint32_t)(wn + b_row) * (PH * 2) + b_byte;
    const uint32_t b_rel1 = b_rel0 + 16 * (PH * 2);

    // ---- stage loader: W 64x64 fp32 (4 cp/thread) + X 64x64 fp16 (2 cp/thread) ----
    auto load_stage = [&](int chunk, int stage) {
        const float* a_base; int a_stride;
        const __half* b_base; int b_stride;
        int k0;
        if (chunk < NCHUNK_MAIN) {
            a_base = w + (size_t)m_base * IN_F;  a_stride = IN_F;
            b_base = xh;                         b_stride = IN_F;
            k0 = chunk * KBLK;
        } else {
            a_base = lB + (size_t)m_base * RANK; a_stride = RANK;
            b_base = t2h;                        b_stride = RANK;
            k0 = 0;
        }
        uint32_t s_w = sb + OFF_W32 + (uint32_t)stage * W32_STAGE_B;
#pragma unroll
        for (int i = 0; i < 4; ++i) {
            int idx = tid + i * THREADS;
            int row = idx >> 4, c = idx & 15;
            cp16(s_w + (uint32_t)(row * P32 + c * 4) * 4,
                 a_base + (size_t)row * a_stride + k0 + c * 4);
        }
        uint32_t s_x = sb + OFF_XH + (uint32_t)stage * XH_STAGE_B;
#pragma unroll
        for (int i = 0; i < 2; ++i) {
            int idx = tid + i * THREADS;
            int row = idx >> 3, seg = idx & 7;
            cp16(s_x + (uint32_t)(row * PH + seg * 8) * 2,
                 b_base + (size_t)row * b_stride + k0 + seg * 8);
        }
    };

    // ---- convert: W32[slot] -> Wh; thread = (row = tid&63, q = tid>>6), 16 floats --
    const int cvt_row = tid & 63;
    const int cvt_q   = tid >> 6;       // 0..3
    auto convert = [&](int slot) {
        const float* srcp = smem_f + slot * W32_STAGE_F + cvt_row * P32 + cvt_q * 16;
        __half* whp = (__half*)(smem_c + OFF_WH) + cvt_row * PH + cvt_q * 16;
        float4 v0 = ((const float4*)srcp)[0];
        float4 v1 = ((const float4*)srcp)[1];
        float4 v2 = ((const float4*)srcp)[2];
        float4 v3 = ((const float4*)srcp)[3];
        uint4 p0, p1;
        p0.x = h2u(__floats2half2_rn(v0.x, v0.y));
        p0.y = h2u(__floats2half2_rn(v0.z, v0.w));
        p0.z = h2u(__floats2half2_rn(v1.x, v1.y));
        p0.w = h2u(__floats2half2_rn(v1.z, v1.w));
        p1.x = h2u(__floats2half2_rn(v2.x, v2.y));
        p1.y = h2u(__floats2half2_rn(v2.z, v2.w));
        p1.z = h2u(__floats2half2_rn(v3.x, v3.y));
        p1.w = h2u(__floats2half2_rn(v3.z, v3.w));
        ((uint4*)whp)[0] = p0;
        ((uint4*)(whp + 8))[0] = p1;
    };

    // ---- prologue: chunks 0,1 in flight ----
    load_stage(0, 0); CP_COMMIT();
    load_stage(1, 1); CP_COMMIT();

    float d[4][4];
#pragma unroll
    for (int ni = 0; ni < 4; ++ni)
#pragma unroll
        for (int r = 0; r < 4; ++r) d[ni][r] = 0.f;

    // ---- mainloop: 65 iterations, two barriers each (R10 schedule, 3 stages) ----
    // top of iter it: committed groups = chunks 0..it+1; wait(1) -> chunks <= it done.
    for (int it = 0; it < NCHUNK_TOT; ++it) {
        const int s = it % 3;
        CP_WAIT1();
        __syncthreads();   // chunk `it` visible to ALL; prior reads of slot s done

        // refill chunk it+2 into slot (it+2)%3 (chunk it-1's slot; reads done)
        {
            int nc = it + 2;
            if (nc < NCHUNK_TOT) load_stage(nc, nc % 3);
            CP_COMMIT();
        }

        convert(s);        // W32[s] -> Wh (covered by wait+barrier above)
        __syncthreads();   // Wh published

        const uint32_t wh_b = sb + OFF_WH;
        const uint32_t xb   = sb + OFF_XH + (uint32_t)s * XH_STAGE_B;
#pragma unroll
        for (int kk = 0; kk < 4; ++kk) {
            const uint32_t k2 = kk * 32;   // 16 halfs = 32B
            uint32_t a0[4], bq0[4], bq1[4];
            ldsm4(a0,  wh_b + a_rel + k2);
            ldsm4(bq0, xb + b_rel0 + k2);
            ldsm4(bq1, xb + b_rel1 + k2);
            mma_f16(d[0], a0, bq0[0], bq0[1]);
            mma_f16(d[1], a0, bq0[2], bq0[3]);
            mma_f16(d[2], a0, bq1[0], bq1[1]);
            mma_f16(d[3], a0, bq1[2], bq1[3]);
        }
    }

    // ---- epilogue: D[m][n] -> out[n][m] ----
#pragma unroll
    for (int ni = 0; ni < 4; ++ni) {
        int m = m_base + wm + g;
        int n = wn + ni * 8 + 2 * t;
        out[(size_t)n * OUT_F + m]           = d[ni][0];
        out[(size_t)(n + 1) * OUT_F + m]     = d[ni][1];
        out[(size_t)n * OUT_F + m + 8]       = d[ni][2];
        out[(size_t)(n + 1) * OUT_F + m + 8] = d[ni][3];
    }
}

// ---------------- host launch ----------------
extern "C" void kernel_launch(void* const* d_in, const int* in_sizes, int n_in,
                              void* d_out, int out_size) {
    const float* x  = (const float*)d_in[0];   // [64, 4096]
    const float* w  = (const float*)d_in[1];   // [16384, 4096]
    const float* lA = (const float*)d_in[2];   // [64, 4096]
    const float* lB = (const float*)d_in[3];   // [16384, 64]
    float* out = (float*)d_out;                // [64, 16384]

    void* xh_ptr = nullptr;
    void* t2_ptr = nullptr;
    void* part_ptr = nullptr;
    cudaGetSymbolAddress(&xh_ptr, g_xh);
    cudaGetSymbolAddress(&t2_ptr, g_t2h);
    cudaGetSymbolAddress(&part_ptr, g_part);

    prep_kernel<<<64, 256>>>(x, lA, (uint2*)xh_ptr, (float*)part_ptr);
    reduce_kernel<<<16, 256>>>((const float*)part_ptr, (__half*)t2_ptr);

    static int smem_set = 0;
    if (!smem_set) {
        cudaFuncSetAttribute(lora_main_kernel,
                             cudaFuncAttributeMaxDynamicSharedMemorySize, SMEM_BYTES);
        smem_set = 1;
    }
    lora_main_kernel<<<OUT_F / BLOCK_M, THREADS, SMEM_BYTES>>>(
        (const __half*)xh_ptr, w, lB, (const __half*)t2_ptr, out);
}

// round 17
// speedup vs baseline: 1.0436x; 1.0007x over previous
#include <cuda_runtime.h>
#include <cuda_fp16.h>
#include <cstdint>

// ---------------- problem constants ----------------
#define IN_F   4096
#define OUT_F  16384
#define NTOK   64
#define RANK   64

#define BLOCK_M 64           // out-features per CTA (2 CTAs/SM)
#define KBLK    64           // K elems per pipeline stage
#define STAGES  3
#define THREADS 256
#define NCHUNK_MAIN (IN_F / KBLK)             // 64
#define NCHUNK_TOT  (NCHUNK_MAIN + 1)         // 65 (lora tail chunk)

#define NSLICE 128                             // prep K-slices (K=32 each)

// ---------------- main-kernel SMEM layout (89 KB -> 2 CTAs/SM) ----------------
#define P32        68                          // fp32 row pitch (floats)
#define W32_STAGE_F (BLOCK_M * P32)            // 4352 floats
#define W32_STAGE_B (W32_STAGE_F * 4)          // 17408 B
#define OFF_W32    0
#define PH         72                          // fp16 row pitch (halfs)
#define OFF_WH     (STAGES * W32_STAGE_B)      // 52224  (single buffer)
#define WH_BYTES   (BLOCK_M * PH * 2)          // 9216
#define OFF_XH     (OFF_WH + WH_BYTES)         // 61440
#define XH_STAGE_B (NTOK * PH * 2)             // 9216
#define SMEM_BYTES (OFF_XH + STAGES * XH_STAGE_B)  // 89088

// device scratch
__device__ __align__(256) __half g_xh[NTOK * IN_F];    // x in fp16
__device__ __align__(256) __half g_t2h[NTOK * RANK];   // 2*(x@A^T) in fp16
__device__ __align__(256) float  g_part[NSLICE * NTOK * RANK];  // K-slice partials

// ---------------- PTX helpers ----------------
__device__ __forceinline__ uint32_t smem_u32(const void* p) {
    uint32_t a;
    asm("{ .reg .u64 t; cvta.to.shared.u64 t, %1; cvt.u32.u64 %0, t; }" : "=r"(a) : "l"(p));
    return a;
}
__device__ __forceinline__ void cp16(uint32_t dst, const void* src) {
    asm volatile("cp.async.cg.shared.global [%0], [%1], 16;" :: "r"(dst), "l"(src));
}
#define CP_COMMIT() asm volatile("cp.async.commit_group;" ::: "memory")
#define CP_WAIT1()  asm volatile("cp.async.wait_group 1;" ::: "memory")

__device__ __forceinline__ void ldsm4(uint32_t* r, uint32_t addr) {
    asm volatile("ldmatrix.sync.aligned.m8n8.x4.shared.b16 {%0,%1,%2,%3}, [%4];"
                 : "=r"(r[0]), "=r"(r[1]), "=r"(r[2]), "=r"(r[3]) : "r"(addr));
}
__device__ __forceinline__ void mma_f16(float* d, const uint32_t* a,
                                        uint32_t b0, uint32_t b1) {
    asm volatile(
        "mma.sync.aligned.m16n8k16.row.col.f32.f16.f16.f32 "
        "{%0,%1,%2,%3}, {%4,%5,%6,%7}, {%8,%9}, {%0,%1,%2,%3};"
        : "+f"(d[0]), "+f"(d[1]), "+f"(d[2]), "+f"(d[3])
        : "r"(a[0]), "r"(a[1]), "r"(a[2]), "r"(a[3]), "r"(b0), "r"(b1));
}
__device__ __forceinline__ uint32_t h2u(__half2 h) {
    return *reinterpret_cast<uint32_t*>(&h);
}
__device__ __forceinline__ float dot4(float4 a, float4 b) {
    return a.x * b.x + a.y * b.y + a.z * b.z + a.w * b.w;
}

// ---------------- prep: grid 128 (one wave). x2h share + t2 K-slice(32) partial -----
__global__ void __launch_bounds__(256) prep_kernel(const float* __restrict__ x,
                                                   const float* __restrict__ A,
                                                   uint2* __restrict__ xh2,
                                                   float* __restrict__ part) {
    int tid = threadIdx.x;
    int s = blockIdx.x;                       // 0..127 (K-slice of 32)
    // ---- x -> fp16: 65536 float4 over 128 blocks = 2/thread ----
    {
        const float4* x4 = (const float4*)x;
        int base = s * 512;
#pragma unroll
        for (int i = 0; i < 2; ++i) {
            int idx = base + tid + i * 256;
            float4 v = x4[idx];
            uint2 o;
            o.x = h2u(__floats2half2_rn(v.x, v.y));
            o.y = h2u(__floats2half2_rn(v.z, v.w));
            xh2[idx] = o;
        }
    }
    // ---- t2 partial for K-slice s (32 floats = 8 float4 per row) ----
    __shared__ float4 xs[64][9];              // 8 f4 + 1 pad
    __shared__ float4 as[64][9];
    // 512 f4 per tile, 2 per thread
#pragma unroll
    for (int i = 0; i < 2; ++i) {
        int idx = tid + i * 256;
        int row = idx >> 3, c = idx & 7;
        xs[row][c] = ((const float4*)x)[(size_t)row * (IN_F / 4) + s * 8 + c];
        as[row][c] = ((const float4*)A)[(size_t)row * (IN_F / 4) + s * 8 + c];
    }
    __syncthreads();
    int ti = tid >> 4, tj = tid & 15;
    float acc[4][4];
#pragma unroll
    for (int r = 0; r < 4; ++r)
#pragma unroll
        for (int c = 0; c < 4; ++c) acc[r][c] = 0.f;
#pragma unroll
    for (int kc = 0; kc < 8; ++kc) {
        float4 xv[4], av[4];
#pragma unroll
        for (int r = 0; r < 4; ++r) xv[r] = xs[ti * 4 + r][kc];
#pragma unroll
        for (int c = 0; c < 4; ++c) av[c] = as[tj * 4 + c][kc];
#pragma unroll
        for (int r = 0; r < 4; ++r)
#pragma unroll
            for (int c = 0; c < 4; ++c) acc[r][c] += dot4(xv[r], av[c]);
    }
    float* dst = part + (size_t)s * (NTOK * RANK);
#pragma unroll
    for (int r = 0; r < 4; ++r)
#pragma unroll
        for (int c = 0; c < 4; ++c)
            dst[(ti * 4 + r) * RANK + tj * 4 + c] = acc[r][c];
}

// ---------------- reduce: 128 partials -> t2h = fp16(2*sum); 8-way MLP ------------
__global__ void __launch_bounds__(256) reduce_kernel(const float* __restrict__ part,
                                                     __half* __restrict__ t2) {
    int idx = blockIdx.x * 256 + threadIdx.x;     // 0..4095
    float s[8];
#pragma unroll
    for (int j = 0; j < 8; ++j) s[j] = 0.f;
#pragma unroll
    for (int b = 0; b < NSLICE; b += 8)
#pragma unroll
        for (int j = 0; j < 8; ++j)
            s[j] += part[(size_t)(b + j) * 4096 + idx];
    float r = ((s[0] + s[1]) + (s[2] + s[3])) + ((s[4] + s[5]) + (s[6] + s[7]));
    t2[idx] = __float2half_rn(2.0f * r);
}

// ---------------- main fused GEMM (FROZEN — R16 baseline, 90.3us total) ----------
// 256 CTAs (2/SM via 89KB smem), 256 threads (8 warps: 4M x 2N), KBLK=64, 3 stages.
__global__ void __launch_bounds__(THREADS, 2) lora_main_kernel(
    const __half* __restrict__ xh,     // [64,4096] fp16
    const float*  __restrict__ w,      // [16384,4096] fp32
    const float*  __restrict__ lB,     // [16384,64] fp32
    const __half* __restrict__ t2h,    // [64,64] fp16 (incl. 2x scale)
    float* __restrict__ out)           // [64,16384]
{
    extern __shared__ __align__(16) char smem_c[];
    float* smem_f = (float*)smem_c;
    const uint32_t sb = smem_u32(smem_c);
    const int tid  = threadIdx.x;
    const int wid  = tid >> 5;
    const int lane = tid & 31;
    const int g = lane >> 2;
    const int t = lane & 3;
    const int wm = (wid & 3) * 16;    // warp M offset (4 warps x 16 rows)
    const int wn = (wid >> 2) * 32;   // warp N offset (tokens)
    const int m_base = blockIdx.x * BLOCK_M;

    // ---- per-lane ldmatrix offsets ----
    const int a_row  = (lane & 7) + ((lane >> 3) & 1) * 8;
    const uint32_t a_byte = ((lane >> 4) & 1) * 16;
    const uint32_t a_rel = (uint32_t)(wm + a_row) * (PH * 2) + a_byte;
    const int b_row  = (lane & 7) + ((lane >> 4) & 1) * 8;
    const uint32_t b_byte = ((lane >> 3) & 1) * 16;
    const uint32_t b_rel0 = (uint32_t)(wn + b_row) * (PH * 2) + b_byte;
    const uint32_t b_rel1 = b_rel0 + 16 * (PH * 2);

    // ---- stage loader: W 64x64 fp32 (4 cp/thread) + X 64x64 fp16 (2 cp/thread) ----
    auto load_stage = [&](int chunk, int stage) {
        const float* a_base; int a_stride;
        const __half* b_base; int b_stride;
        int k0;
        if (chunk < NCHUNK_MAIN) {
            a_base = w + (size_t)m_base * IN_F;  a_stride = IN_F;
            b_base = xh;                         b_stride = IN_F;
            k0 = chunk * KBLK;
        } else {
            a_base = lB + (size_t)m_base * RANK; a_stride = RANK;
            b_base = t2h;                        b_stride = RANK;
            k0 = 0;
        }
        uint32_t s_w = sb + OFF_W32 + (uint32_t)stage * W32_STAGE_B;
#pragma unroll
        for (int i = 0; i < 4; ++i) {
            int idx = tid + i * THREADS;
            int row = idx >> 4, c = idx & 15;
            cp16(s_w + (uint32_t)(row * P32 + c * 4) * 4,
                 a_base + (size_t)row * a_stride + k0 + c * 4);
        }
        uint32_t s_x = sb + OFF_XH + (uint32_t)stage * XH_STAGE_B;
#pragma unroll
        for (int i = 0; i < 2; ++i) {
            int idx = tid + i * THREADS;
            int row = idx >> 3, seg = idx & 7;
            cp16(s_x + (uint32_t)(row * PH + seg * 8) * 2,
                 b_base + (size_t)row * b_stride + k0 + seg * 8);
        }
    };

    // ---- convert: W32[slot] -> Wh; thread = (row = tid&63, q = tid>>6), 16 floats --
    const int cvt_row = tid & 63;
    const int cvt_q   = tid >> 6;       // 0..3
    auto convert = [&](int slot) {
        const float* srcp = smem_f + slot * W32_STAGE_F + cvt_row * P32 + cvt_q * 16;
        __half* whp = (__half*)(smem_c + OFF_WH) + cvt_row * PH + cvt_q * 16;
        float4 v0 = ((const float4*)srcp)[0];
        float4 v1 = ((const float4*)srcp)[1];
        float4 v2 = ((const float4*)srcp)[2];
        float4 v3 = ((const float4*)srcp)[3];
        uint4 p0, p1;
        p0.x = h2u(__floats2half2_rn(v0.x, v0.y));
        p0.y = h2u(__floats2half2_rn(v0.z, v0.w));
        p0.z = h2u(__floats2half2_rn(v1.x, v1.y));
        p0.w = h2u(__floats2half2_rn(v1.z, v1.w));
        p1.x = h2u(__floats2half2_rn(v2.x, v2.y));
        p1.y = h2u(__floats2half2_rn(v2.z, v2.w));
        p1.z = h2u(__floats2half2_rn(v3.x, v3.y));
        p1.w = h2u(__floats2half2_rn(v3.z, v3.w));
        ((uint4*)whp)[0] = p0;
        ((uint4*)(whp + 8))[0] = p1;
    };

    // ---- prologue: chunks 0,1 in flight ----
    load_stage(0, 0); CP_COMMIT();
    load_stage(1, 1); CP_COMMIT();

    float d[4][4];
#pragma unroll
    for (int ni = 0; ni < 4; ++ni)
#pragma unroll
        for (int r = 0; r < 4; ++r) d[ni][r] = 0.f;

    // ---- mainloop: 65 iterations, two barriers each ----
    for (int it = 0; it < NCHUNK_TOT; ++it) {
        const int s = it % 3;
        CP_WAIT1();
        __syncthreads();   // chunk `it` visible to ALL; prior reads of slot s done

        {
            int nc = it + 2;
            if (nc < NCHUNK_TOT) load_stage(nc, nc % 3);
            CP_COMMIT();
        }

        convert(s);
        __syncthreads();   // Wh published

        const uint32_t wh_b = sb + OFF_WH;
        const uint32_t xb   = sb + OFF_XH + (uint32_t)s * XH_STAGE_B;
#pragma unroll
        for (int kk = 0; kk < 4; ++kk) {
            const uint32_t k2 = kk * 32;   // 16 halfs = 32B
            uint32_t a0[4], bq0[4], bq1[4];
            ldsm4(a0,  wh_b + a_rel + k2);
            ldsm4(bq0, xb + b_rel0 + k2);
            ldsm4(bq1, xb + b_rel1 + k2);
            mma_f16(d[0], a0, bq0[0], bq0[1]);
            mma_f16(d[1], a0, bq0[2], bq0[3]);
            mma_f16(d[2], a0, bq1[0], bq1[1]);
            mma_f16(d[3], a0, bq1[2], bq1[3]);
        }
    }

    // ---- epilogue: D[m][n] -> out[n][m] ----
#pragma unroll
    for (int ni = 0; ni < 4; ++ni) {
        int m = m_base + wm + g;
        int n = wn + ni * 8 + 2 * t;
        out[(size_t)n * OUT_F + m]           = d[ni][0];
        out[(size_t)(n + 1) * OUT_F + m]     = d[ni][1];
        out[(size_t)n * OUT_F + m + 8]       = d[ni][2];
        out[(size_t)(n + 1) * OUT_F + m + 8] = d[ni][3];
    }
}

// ---------------- host launch ----------------
extern "C" void kernel_launch(void* const* d_in, const int* in_sizes, int n_in,
                              void* d_out, int out_size) {
    const float* x  = (const float*)d_in[0];   // [64, 4096]
    const float* w  = (const float*)d_in[1];   // [16384, 4096]
    const float* lA = (const float*)d_in[2];   // [64, 4096]
    const float* lB = (const float*)d_in[3];   // [16384, 64]
    float* out = (float*)d_out;                // [64, 16384]

    void* xh_ptr = nullptr;
    void* t2_ptr = nullptr;
    void* part_ptr = nullptr;
    cudaGetSymbolAddress(&xh_ptr, g_xh);
    cudaGetSymbolAddress(&t2_ptr, g_t2h);
    cudaGetSymbolAddress(&part_ptr, g_part);

    prep_kernel<<<NSLICE, 256>>>(x, lA, (uint2*)xh_ptr, (float*)part_ptr);
    reduce_kernel<<<16, 256>>>((const float*)part_ptr, (__half*)t2_ptr);

    static int smem_set = 0;
    if (!smem_set) {
        cudaFuncSetAttribute(lora_main_kernel,
                             cudaFuncAttributeMaxDynamicSharedMemorySize, SMEM_BYTES);
        smem_set = 1;
    }
    lora_main_kernel<<<OUT_F / BLOCK_M, THREADS, SMEM_BYTES>>>(
        (const __half*)xh_ptr, w, lB, (const __half*)t2_ptr, out);
}